// round 15
// baseline (speedup 1.0000x reference)
#include <cuda_runtime.h>
#include <cuda_bf16.h>

// ---------------------------------------------------------------------------
// Static scratch (allocation-free rule: __device__ globals)
// N=60000, F_IN=512, F_OUT=128 for this problem instance.
// ---------------------------------------------------------------------------
#define MAXN 60000
#define FIN  512
#define FOUT 128

__device__ float g_h [(size_t)MAXN * FIN];   // lin1 output
__device__ float g_s0[(size_t)MAXN * FIN];   // P1 stage-0 accumulator
__device__ float g_s1[(size_t)MAXN * FIN];   // P1 stage-1 accumulator
__device__ float g_h2[(size_t)MAXN * FOUT];  // lin2 output
__device__ float g_pb[(size_t)MAXN * FOUT];  // P2 stage-1 accumulator

// ---------------------------------------------------------------------------
// Packed f32x2 helpers (B300: scalar FFMA rt_SMSP=2 -> fp32 peak needs f32x2)
// ---------------------------------------------------------------------------
__device__ __forceinline__ unsigned long long dup_f32x2(float x) {
    unsigned long long r;
    unsigned int xi = __float_as_uint(x);
    asm("mov.b64 %0, {%1, %1};" : "=l"(r) : "r"(xi));
    return r;
}
__device__ __forceinline__ unsigned long long pack_f32x2(float x, float y) {
    unsigned long long r;
    asm("mov.b64 %0, {%1, %2};" : "=l"(r)
        : "r"(__float_as_uint(x)), "r"(__float_as_uint(y)));
    return r;
}
__device__ __forceinline__ void fma2(unsigned long long& c,
                                     unsigned long long a,
                                     unsigned long long b) {
    asm("fma.rn.f32x2 %0, %1, %2, %0;" : "+l"(c) : "l"(a), "l"(b));
}
__device__ __forceinline__ float2 unpack_f32x2(unsigned long long v) {
    unsigned int lo, hi;
    asm("mov.b64 {%0, %1}, %2;" : "=r"(lo), "=r"(hi) : "l"(v));
    float2 f;
    f.x = __uint_as_float(lo);
    f.y = __uint_as_float(hi);
    return f;
}

// ---------------------------------------------------------------------------
// SGEMM: C[M,N] = op(A)[M,K] @ B[K,N] + bias[N]
//   FUSE=false: op(A) = A
//   FUSE=true : op(A)[i] = relu(A[i] + A2[i])   (fused P1-combine + relu)
// Tiles: BM=BN=128, BK=16, 256 threads, 8x8 micro-tile, f32x2 accumulators.
// ---------------------------------------------------------------------------
#define BM 128
#define BN 128
#define BK 16

template <bool FUSE>
__global__ __launch_bounds__(256, 2)
void sgemm_kernel(const float* __restrict__ A, const float* __restrict__ A2,
                  const float* __restrict__ B, const float* __restrict__ bias,
                  float* __restrict__ C, int M, int N, int K)
{
    __shared__ float As[BK * BM];   // transposed: As[k*BM + m]
    __shared__ float Bs[BK * BN];   // Bs[k*BN + n]

    const int tid = threadIdx.x;
    const int tx  = tid & 15;       // 0..15 -> 8 output cols each
    const int ty  = tid >> 4;       // 0..15 -> 8 output rows each
    const long bm0 = (long)blockIdx.y * BM;
    const long bn0 = (long)blockIdx.x * BN;

    unsigned long long acc[8][4];   // 8 rows x 4 f32x2 pairs (= 8 cols)
    #pragma unroll
    for (int i = 0; i < 8; i++)
        #pragma unroll
        for (int j = 0; j < 4; j++)
            acc[i][j] = 0ull;       // bit pattern of {0.f, 0.f}

    const int nIter = K / BK;
    for (int it = 0; it < nIter; ++it) {
        const int k0 = it * BK;

        // ---- load A tile (transpose into As) : 2 float4 per thread ----
        #pragma unroll
        for (int l = 0; l < 2; l++) {
            int f   = tid + l * 256;        // 0..511
            int row = f >> 2;               // 0..127
            int c4  = (f & 3) * 4;          // 0,4,8,12
            long gr = bm0 + row;
            float4 av = make_float4(0.f, 0.f, 0.f, 0.f);
            if (gr < M) {
                av = *(const float4*)(A + gr * (long)K + k0 + c4);
                if (FUSE) {
                    float4 a2 = *(const float4*)(A2 + gr * (long)K + k0 + c4);
                    av.x = fmaxf(av.x + a2.x, 0.f);
                    av.y = fmaxf(av.y + a2.y, 0.f);
                    av.z = fmaxf(av.z + a2.z, 0.f);
                    av.w = fmaxf(av.w + a2.w, 0.f);
                }
            }
            As[(c4 + 0) * BM + row] = av.x;
            As[(c4 + 1) * BM + row] = av.y;
            As[(c4 + 2) * BM + row] = av.z;
            As[(c4 + 3) * BM + row] = av.w;
        }
        // ---- load B tile : 2 float4 per thread ----
        #pragma unroll
        for (int l = 0; l < 2; l++) {
            int f  = tid + l * 256;         // 0..511
            int kr = f >> 5;                // 0..15
            int n4 = (f & 31) * 4;          // 0..124
            float4 bv = *(const float4*)(B + (long)(k0 + kr) * N + bn0 + n4);
            *(float4*)(Bs + kr * BN + n4) = bv;
        }
        __syncthreads();

        // ---- compute: 16 k-steps, 32 fma2 each ----
        #pragma unroll
        for (int k = 0; k < BK; k++) {
            float4 a0 = *(const float4*)(As + k * BM + ty * 8);
            float4 a1 = *(const float4*)(As + k * BM + ty * 8 + 4);
            float4 b0 = *(const float4*)(Bs + k * BN + tx * 8);
            float4 b1 = *(const float4*)(Bs + k * BN + tx * 8 + 4);

            unsigned long long bb[4];
            bb[0] = pack_f32x2(b0.x, b0.y);
            bb[1] = pack_f32x2(b0.z, b0.w);
            bb[2] = pack_f32x2(b1.x, b1.y);
            bb[3] = pack_f32x2(b1.z, b1.w);

            float av[8] = {a0.x, a0.y, a0.z, a0.w, a1.x, a1.y, a1.z, a1.w};
            #pragma unroll
            for (int i = 0; i < 8; i++) {
                unsigned long long ad = dup_f32x2(av[i]);
                fma2(acc[i][0], ad, bb[0]);
                fma2(acc[i][1], ad, bb[1]);
                fma2(acc[i][2], ad, bb[2]);
                fma2(acc[i][3], ad, bb[3]);
            }
        }
        __syncthreads();
    }

    // ---- epilogue: bias + store ----
    float4 bv0 = *(const float4*)(bias + bn0 + tx * 8);
    float4 bv1 = *(const float4*)(bias + bn0 + tx * 8 + 4);
    #pragma unroll
    for (int i = 0; i < 8; i++) {
        long gr = bm0 + ty * 8 + i;
        if (gr < M) {
            float2 p0 = unpack_f32x2(acc[i][0]);
            float2 p1 = unpack_f32x2(acc[i][1]);
            float2 p2 = unpack_f32x2(acc[i][2]);
            float2 p3 = unpack_f32x2(acc[i][3]);
            float4 o0 = make_float4(p0.x + bv0.x, p0.y + bv0.y,
                                    p1.x + bv0.z, p1.y + bv0.w);
            float4 o1 = make_float4(p2.x + bv1.x, p2.y + bv1.y,
                                    p3.x + bv1.z, p3.y + bv1.w);
            float* cp = C + gr * (long)N + bn0 + tx * 8;
            *(float4*)(cp)     = o0;
            *(float4*)(cp + 4) = o1;
        }
    }
}

// ---------------------------------------------------------------------------
// Masked scatter-add: for edges with mask==step, out[dst] += cur[src]
// INT32 indices (JAX x64-disabled downcasts the reference's int64 to int32).
// lanes = F/4 threads per edge, float4 gather, 4 scalar fp32 atomics
// (return value unused -> ptxas emits REDG, no round-trip).
// ---------------------------------------------------------------------------
__global__ void scatter_kernel(const float* __restrict__ cur,
                               float* __restrict__ out,
                               const int* __restrict__ src,
                               const int* __restrict__ dst,
                               const int* __restrict__ mask,
                               int E, int F, int step)
{
    const int lanes = F >> 2;                       // threads per edge
    const int epb   = blockDim.x / lanes;           // edges per block
    const int local = threadIdx.x / lanes;
    const int t     = threadIdx.x - local * lanes;  // feature chunk id
    const int e     = blockIdx.x * epb + local;
    if (e >= E) return;
    if (mask[e] != step) return;

    const long s = (long)src[e];
    const long d = (long)dst[e];
    const float4 v = *(const float4*)(cur + s * (long)F + t * 4);
    float* o = out + d * (long)F + t * 4;
    atomicAdd(o + 0, v.x);
    atomicAdd(o + 1, v.y);
    atomicAdd(o + 2, v.z);
    atomicAdd(o + 3, v.w);
}

// ---------------------------------------------------------------------------
// Utility kernels
// ---------------------------------------------------------------------------
__global__ void zero_kernel(float* __restrict__ p, size_t n)
{
    size_t n4 = n >> 2;
    size_t stride = (size_t)gridDim.x * blockDim.x;
    for (size_t i = (size_t)blockIdx.x * blockDim.x + threadIdx.x;
         i < n4; i += stride)
        ((float4*)p)[i] = make_float4(0.f, 0.f, 0.f, 0.f);
}

__global__ void add_kernel(float* __restrict__ a, const float* __restrict__ b,
                           size_t n)
{
    size_t n4 = n >> 2;
    size_t stride = (size_t)gridDim.x * blockDim.x;
    for (size_t i = (size_t)blockIdx.x * blockDim.x + threadIdx.x;
         i < n4; i += stride) {
        float4 x = ((const float4*)a)[i];
        float4 y = ((const float4*)b)[i];
        x.x += y.x; x.y += y.y; x.z += y.z; x.w += y.w;
        ((float4*)a)[i] = x;
    }
}

// ---------------------------------------------------------------------------
// kernel_launch
// Input order: x, edge_index, edge_mask, [vertex_cnt, rule_cnt,] W1, b1, W2, b2
// Weights are indexed from the back so optional scalar inputs don't shift them.
// edge_index/edge_mask are INT32 (JAX default x64-disabled).
// ---------------------------------------------------------------------------
extern "C" void kernel_launch(void* const* d_in, const int* in_sizes, int n_in,
                              void* d_out, int out_size)
{
    const float* x  = (const float*)d_in[0];
    const int*   ei = (const int*)d_in[1];
    const int*   em = (const int*)d_in[2];

    const int base = n_in - 4;
    const float* W1 = (const float*)d_in[base + 0];
    const float* b1 = (const float*)d_in[base + 1];
    const float* W2 = (const float*)d_in[base + 2];
    const float* b2 = (const float*)d_in[base + 3];

    const int F_IN  = in_sizes[base + 1];     // 512
    const int F_OUT = in_sizes[base + 3];     // 128
    const int E     = in_sizes[2];            // 160000
    const int Nn    = in_sizes[0] / F_IN;     // 60000

    const int* src = ei;
    const int* dst = ei + E;

    float *p_h, *p_s0, *p_s1, *p_h2, *p_pb;
    cudaGetSymbolAddress((void**)&p_h,  g_h);
    cudaGetSymbolAddress((void**)&p_s0, g_s0);
    cudaGetSymbolAddress((void**)&p_s1, g_s1);
    cudaGetSymbolAddress((void**)&p_h2, g_h2);
    cudaGetSymbolAddress((void**)&p_pb, g_pb);
    float* out = (float*)d_out;

    // ---- 1. h = x @ W1 + b1 ----
    {
        dim3 grid(F_IN / BN, (Nn + BM - 1) / BM);
        sgemm_kernel<false><<<grid, 256>>>(x, nullptr, W1, b1, p_h,
                                           Nn, F_IN, F_IN);
    }

    // ---- 2. P1: s0 = S0(h); s1 = S1(s0); P1 = s0 + s1 ----
    zero_kernel<<<1184, 256>>>(p_s0, (size_t)Nn * F_IN);
    zero_kernel<<<1184, 256>>>(p_s1, (size_t)Nn * F_IN);
    {
        // F=512 -> lanes=128, 256 threads => 2 edges per block
        int lanes = F_IN / 4;
        int epb   = 256 / lanes;              // 2
        int grid  = (E + epb - 1) / epb;      // 80000
        scatter_kernel<<<grid, 256>>>(p_h,  p_s0, src, dst, em, E, F_IN, 0);
        scatter_kernel<<<grid, 256>>>(p_s0, p_s1, src, dst, em, E, F_IN, 1);
    }

    // ---- 3. h2 = relu(s0 + s1) @ W2 + b2  (combine fused into A load) ----
    {
        dim3 grid(F_OUT / BN, (Nn + BM - 1) / BM);
        sgemm_kernel<true><<<grid, 256>>>(p_s0, p_s1, W2, b2, p_h2,
                                          Nn, F_OUT, F_IN);
    }

    // ---- 4. P2: out = S0(h2); pb = S1(out); out += pb ----
    zero_kernel<<<1184, 256>>>(out,  (size_t)Nn * F_OUT);
    zero_kernel<<<1184, 256>>>(p_pb, (size_t)Nn * F_OUT);
    {
        // F=128 -> lanes=32, 256 threads => 8 edges per block
        int lanes = F_OUT / 4;
        int epb   = 256 / lanes;              // 8
        int grid  = (E + epb - 1) / epb;      // 20000
        scatter_kernel<<<grid, 256>>>(p_h2, out,  src, dst, em, E, F_OUT, 0);
        scatter_kernel<<<grid, 256>>>(out,  p_pb, src, dst, em, E, F_OUT, 1);
    }
    add_kernel<<<1184, 256>>>(out, p_pb, (size_t)Nn * F_OUT);
}

// round 16
// speedup vs baseline: 1.5519x; 1.5519x over previous
#include <cuda_runtime.h>
#include <cuda_bf16.h>

// ---------------------------------------------------------------------------
// Static scratch (allocation-free rule: __device__ globals)
// N=60000, F_IN=512, F_OUT=128 for this problem instance.
// ---------------------------------------------------------------------------
#define MAXN 60000
#define FIN  512
#define FOUT 128

__device__ float g_h [(size_t)MAXN * FIN];   // lin1 output
__device__ float g_s0[(size_t)MAXN * FIN];   // P1 stage-0 accumulator
__device__ float g_s1[(size_t)MAXN * FIN];   // P1 stage-1 accumulator
__device__ float g_h2[(size_t)MAXN * FOUT];  // lin2 output
__device__ float g_pb[(size_t)MAXN * FOUT];  // P2 stage-1 accumulator

// ---------------------------------------------------------------------------
// Packed f32x2 helpers (B300: scalar FFMA rt_SMSP=2 -> fp32 peak needs f32x2)
// ---------------------------------------------------------------------------
__device__ __forceinline__ unsigned long long dup_f32x2(float x) {
    unsigned long long r;
    unsigned int xi = __float_as_uint(x);
    asm("mov.b64 %0, {%1, %1};" : "=l"(r) : "r"(xi));
    return r;
}
__device__ __forceinline__ unsigned long long pack_f32x2(float x, float y) {
    unsigned long long r;
    asm("mov.b64 %0, {%1, %2};" : "=l"(r)
        : "r"(__float_as_uint(x)), "r"(__float_as_uint(y)));
    return r;
}
__device__ __forceinline__ void fma2(unsigned long long& c,
                                     unsigned long long a,
                                     unsigned long long b) {
    asm("fma.rn.f32x2 %0, %1, %2, %0;" : "+l"(c) : "l"(a), "l"(b));
}
__device__ __forceinline__ float2 unpack_f32x2(unsigned long long v) {
    unsigned int lo, hi;
    asm("mov.b64 {%0, %1}, %2;" : "=r"(lo), "=r"(hi) : "l"(v));
    float2 f;
    f.x = __uint_as_float(lo);
    f.y = __uint_as_float(hi);
    return f;
}

// ---------------------------------------------------------------------------
// SGEMM: C[M,N] = op(A)[M,K] @ B[K,N] + bias[N]
//   FUSE=false: op(A) = A
//   FUSE=true : op(A)[i] = relu(A[i] + A2[i])   (fused P1-combine + relu)
// Tiles: BM=BN=128, BK=16, 256 threads, 8x8 micro-tile, f32x2 accumulators.
// ---------------------------------------------------------------------------
#define BM 128
#define BN 128
#define BK 16

template <bool FUSE>
__global__ __launch_bounds__(256, 2)
void sgemm_kernel(const float* __restrict__ A, const float* __restrict__ A2,
                  const float* __restrict__ B, const float* __restrict__ bias,
                  float* __restrict__ C, int M, int N, int K)
{
    __shared__ float As[BK * BM];   // transposed: As[k*BM + m]
    __shared__ float Bs[BK * BN];   // Bs[k*BN + n]

    const int tid = threadIdx.x;
    const int tx  = tid & 15;       // 0..15 -> 8 output cols each
    const int ty  = tid >> 4;       // 0..15 -> 8 output rows each
    const long bm0 = (long)blockIdx.y * BM;
    const long bn0 = (long)blockIdx.x * BN;

    unsigned long long acc[8][4];   // 8 rows x 4 f32x2 pairs (= 8 cols)
    #pragma unroll
    for (int i = 0; i < 8; i++)
        #pragma unroll
        for (int j = 0; j < 4; j++)
            acc[i][j] = 0ull;       // bit pattern of {0.f, 0.f}

    const int nIter = K / BK;
    for (int it = 0; it < nIter; ++it) {
        const int k0 = it * BK;

        // ---- load A tile (transpose into As) : 2 float4 per thread ----
        #pragma unroll
        for (int l = 0; l < 2; l++) {
            int f   = tid + l * 256;        // 0..511
            int row = f >> 2;               // 0..127
            int c4  = (f & 3) * 4;          // 0,4,8,12
            long gr = bm0 + row;
            float4 av = make_float4(0.f, 0.f, 0.f, 0.f);
            if (gr < M) {
                av = *(const float4*)(A + gr * (long)K + k0 + c4);
                if (FUSE) {
                    float4 a2 = *(const float4*)(A2 + gr * (long)K + k0 + c4);
                    av.x = fmaxf(av.x + a2.x, 0.f);
                    av.y = fmaxf(av.y + a2.y, 0.f);
                    av.z = fmaxf(av.z + a2.z, 0.f);
                    av.w = fmaxf(av.w + a2.w, 0.f);
                }
            }
            As[(c4 + 0) * BM + row] = av.x;
            As[(c4 + 1) * BM + row] = av.y;
            As[(c4 + 2) * BM + row] = av.z;
            As[(c4 + 3) * BM + row] = av.w;
        }
        // ---- load B tile : 2 float4 per thread ----
        #pragma unroll
        for (int l = 0; l < 2; l++) {
            int f  = tid + l * 256;         // 0..511
            int kr = f >> 5;                // 0..15
            int n4 = (f & 31) * 4;          // 0..124
            float4 bv = *(const float4*)(B + (long)(k0 + kr) * N + bn0 + n4);
            *(float4*)(Bs + kr * BN + n4) = bv;
        }
        __syncthreads();

        // ---- compute: 16 k-steps, 32 fma2 each ----
        #pragma unroll
        for (int k = 0; k < BK; k++) {
            float4 a0 = *(const float4*)(As + k * BM + ty * 8);
            float4 a1 = *(const float4*)(As + k * BM + ty * 8 + 4);
            float4 b0 = *(const float4*)(Bs + k * BN + tx * 8);
            float4 b1 = *(const float4*)(Bs + k * BN + tx * 8 + 4);

            unsigned long long bb[4];
            bb[0] = pack_f32x2(b0.x, b0.y);
            bb[1] = pack_f32x2(b0.z, b0.w);
            bb[2] = pack_f32x2(b1.x, b1.y);
            bb[3] = pack_f32x2(b1.z, b1.w);

            float av[8] = {a0.x, a0.y, a0.z, a0.w, a1.x, a1.y, a1.z, a1.w};
            #pragma unroll
            for (int i = 0; i < 8; i++) {
                unsigned long long ad = dup_f32x2(av[i]);
                fma2(acc[i][0], ad, bb[0]);
                fma2(acc[i][1], ad, bb[1]);
                fma2(acc[i][2], ad, bb[2]);
                fma2(acc[i][3], ad, bb[3]);
            }
        }
        __syncthreads();
    }

    // ---- epilogue: bias + store ----
    float4 bv0 = *(const float4*)(bias + bn0 + tx * 8);
    float4 bv1 = *(const float4*)(bias + bn0 + tx * 8 + 4);
    #pragma unroll
    for (int i = 0; i < 8; i++) {
        long gr = bm0 + ty * 8 + i;
        if (gr < M) {
            float2 p0 = unpack_f32x2(acc[i][0]);
            float2 p1 = unpack_f32x2(acc[i][1]);
            float2 p2 = unpack_f32x2(acc[i][2]);
            float2 p3 = unpack_f32x2(acc[i][3]);
            float4 o0 = make_float4(p0.x + bv0.x, p0.y + bv0.y,
                                    p1.x + bv0.z, p1.y + bv0.w);
            float4 o1 = make_float4(p2.x + bv1.x, p2.y + bv1.y,
                                    p3.x + bv1.z, p3.y + bv1.w);
            float* cp = C + gr * (long)N + bn0 + tx * 8;
            *(float4*)(cp)     = o0;
            *(float4*)(cp + 4) = o1;
        }
    }
}

// ---------------------------------------------------------------------------
// Masked scatter-add: for edges with mask==step, out[dst] += cur[src]
// INT32 indices (JAX x64-disabled downcasts the reference's int64 to int32).
// lanes = F/4 threads per edge, float4 gather, 4 scalar fp32 atomics
// (return value unused -> ptxas emits REDG, no round-trip).
// ---------------------------------------------------------------------------
__global__ void scatter_kernel(const float* __restrict__ cur,
                               float* __restrict__ out,
                               const int* __restrict__ src,
                               const int* __restrict__ dst,
                               const int* __restrict__ mask,
                               int E, int F, int step)
{
    const int lanes = F >> 2;                       // threads per edge
    const int epb   = blockDim.x / lanes;           // edges per block
    const int local = threadIdx.x / lanes;
    const int t     = threadIdx.x - local * lanes;  // feature chunk id
    const int e     = blockIdx.x * epb + local;
    if (e >= E) return;
    if (mask[e] != step) return;

    const long s = (long)src[e];
    const long d = (long)dst[e];
    const float4 v = *(const float4*)(cur + s * (long)F + t * 4);
    float* o = out + d * (long)F + t * 4;
    atomicAdd(o + 0, v.x);
    atomicAdd(o + 1, v.y);
    atomicAdd(o + 2, v.z);
    atomicAdd(o + 3, v.w);
}

// ---------------------------------------------------------------------------
// Utility kernels
// ---------------------------------------------------------------------------
__global__ void zero_kernel(float* __restrict__ p, size_t n)
{
    size_t n4 = n >> 2;
    size_t stride = (size_t)gridDim.x * blockDim.x;
    for (size_t i = (size_t)blockIdx.x * blockDim.x + threadIdx.x;
         i < n4; i += stride)
        ((float4*)p)[i] = make_float4(0.f, 0.f, 0.f, 0.f);
}

__global__ void add_kernel(float* __restrict__ a, const float* __restrict__ b,
                           size_t n)
{
    size_t n4 = n >> 2;
    size_t stride = (size_t)gridDim.x * blockDim.x;
    for (size_t i = (size_t)blockIdx.x * blockDim.x + threadIdx.x;
         i < n4; i += stride) {
        float4 x = ((const float4*)a)[i];
        float4 y = ((const float4*)b)[i];
        x.x += y.x; x.y += y.y; x.z += y.z; x.w += y.w;
        ((float4*)a)[i] = x;
    }
}

// ---------------------------------------------------------------------------
// kernel_launch
// Input order: x, edge_index, edge_mask, [vertex_cnt, rule_cnt,] W1, b1, W2, b2
// Weights are indexed from the back so optional scalar inputs don't shift them.
// edge_index/edge_mask are INT32 (JAX default x64-disabled).
// ---------------------------------------------------------------------------
extern "C" void kernel_launch(void* const* d_in, const int* in_sizes, int n_in,
                              void* d_out, int out_size)
{
    const float* x  = (const float*)d_in[0];
    const int*   ei = (const int*)d_in[1];
    const int*   em = (const int*)d_in[2];

    const int base = n_in - 4;
    const float* W1 = (const float*)d_in[base + 0];
    const float* b1 = (const float*)d_in[base + 1];
    const float* W2 = (const float*)d_in[base + 2];
    const float* b2 = (const float*)d_in[base + 3];

    const int F_IN  = in_sizes[base + 1];     // 512
    const int F_OUT = in_sizes[base + 3];     // 128
    const int E     = in_sizes[2];            // 160000
    const int Nn    = in_sizes[0] / F_IN;     // 60000

    const int* src = ei;
    const int* dst = ei + E;

    float *p_h, *p_s0, *p_s1, *p_h2, *p_pb;
    cudaGetSymbolAddress((void**)&p_h,  g_h);
    cudaGetSymbolAddress((void**)&p_s0, g_s0);
    cudaGetSymbolAddress((void**)&p_s1, g_s1);
    cudaGetSymbolAddress((void**)&p_h2, g_h2);
    cudaGetSymbolAddress((void**)&p_pb, g_pb);
    float* out = (float*)d_out;

    // ---- 1. h = x @ W1 + b1 ----
    {
        dim3 grid(F_IN / BN, (Nn + BM - 1) / BM);
        sgemm_kernel<false><<<grid, 256>>>(x, nullptr, W1, b1, p_h,
                                           Nn, F_IN, F_IN);
    }

    // ---- 2. P1: s0 = S0(h); s1 = S1(s0); P1 = s0 + s1 ----
    zero_kernel<<<1184, 256>>>(p_s0, (size_t)Nn * F_IN);
    zero_kernel<<<1184, 256>>>(p_s1, (size_t)Nn * F_IN);
    {
        // F=512 -> lanes=128, 256 threads => 2 edges per block
        int lanes = F_IN / 4;
        int epb   = 256 / lanes;              // 2
        int grid  = (E + epb - 1) / epb;      // 80000
        scatter_kernel<<<grid, 256>>>(p_h,  p_s0, src, dst, em, E, F_IN, 0);
        scatter_kernel<<<grid, 256>>>(p_s0, p_s1, src, dst, em, E, F_IN, 1);
    }

    // ---- 3. h2 = relu(s0 + s1) @ W2 + b2  (combine fused into A load) ----
    {
        dim3 grid(F_OUT / BN, (Nn + BM - 1) / BM);
        sgemm_kernel<true><<<grid, 256>>>(p_s0, p_s1, W2, b2, p_h2,
                                          Nn, F_OUT, F_IN);
    }

    // ---- 4. P2: out = S0(h2); pb = S1(out); out += pb ----
    zero_kernel<<<1184, 256>>>(out,  (size_t)Nn * F_OUT);
    zero_kernel<<<1184, 256>>>(p_pb, (size_t)Nn * F_OUT);
    {
        // F=128 -> lanes=32, 256 threads => 8 edges per block
        int lanes = F_OUT / 4;
        int epb   = 256 / lanes;              // 8
        int grid  = (E + epb - 1) / epb;      // 20000
        scatter_kernel<<<grid, 256>>>(p_h2, out,  src, dst, em, E, F_OUT, 0);
        scatter_kernel<<<grid, 256>>>(out,  p_pb, src, dst, em, E, F_OUT, 1);
    }
    add_kernel<<<1184, 256>>>(out, p_pb, (size_t)Nn * F_OUT);
}